// round 14
// baseline (speedup 1.0000x reference)
#include <cuda_runtime.h>
#include <cuda_fp16.h>
#include <math.h>
#include <stdint.h>

#define BB 2
#define LL 2048
#define DM 1024
#define NH 16
#define HD 64
#define DFF 4096
#define NTOK (BB*LL)
#define LN_EPS 1e-5f

// ---------------- scratch (no allocation allowed) ----------------
__device__ float  g_x2 [NTOK*DM];
__device__ __half g_xh [NTOK*DM];
__device__ __half g_xnh[NTOK*DM];
__device__ __half g_qh [NTOK*DM];
__device__ __half g_kh [NTOK*DM];
__device__ __half g_vh [NTOK*DM];
__device__ __half g_oh [NTOK*DM];
__device__ __half g_xn2h[NTOK*DM];
__device__ __half g_hbh[NTOK*DFF];
// transposed half weights [N][K]
__device__ __half g_wqh[DM*DM];
__device__ __half g_wkh[DM*DM];
__device__ __half g_wvh[DM*DM];
__device__ __half g_woh[DM*DM];
__device__ __half g_w1h[DFF*DM];
__device__ __half g_w2h[DM*DFF];
// rope tables
__device__ float g_cs[LL*32];
__device__ float g_sn[LL*32];

// ---------------- helpers ----------------
__device__ __forceinline__ void cp16(void* smem, const void* g) {
    unsigned sa = (unsigned)__cvta_generic_to_shared(smem);
    asm volatile("cp.async.cg.shared.global [%0], [%1], 16;" :: "r"(sa), "l"(g));
}
#define CP_COMMIT() asm volatile("cp.async.commit_group;" ::: "memory")
#define CP_WAIT0()  asm volatile("cp.async.wait_group 0;" ::: "memory")
#define CP_WAIT1()  asm volatile("cp.async.wait_group 1;" ::: "memory")

__device__ __forceinline__ void mma16(float& c0, float& c1, float& c2, float& c3,
                                      uint32_t a0, uint32_t a1, uint32_t a2, uint32_t a3,
                                      uint32_t b0, uint32_t b1) {
    asm("mma.sync.aligned.m16n8k16.row.col.f32.f16.f16.f32 "
        "{%0,%1,%2,%3},{%4,%5,%6,%7},{%8,%9},{%0,%1,%2,%3};"
        : "+f"(c0), "+f"(c1), "+f"(c2), "+f"(c3)
        : "r"(a0), "r"(a1), "r"(a2), "r"(a3), "r"(b0), "r"(b1));
}
__device__ __forceinline__ uint32_t pack_h2(float x, float y) {
    uint32_t r;
    asm("cvt.rn.f16x2.f32 %0, %1, %2;" : "=r"(r) : "f"(y), "f"(x));
    return r;
}
__device__ __forceinline__ void ldmx4t(uint32_t& r0, uint32_t& r1, uint32_t& r2, uint32_t& r3,
                                       uint32_t addr) {
    asm volatile("ldmatrix.sync.aligned.m8n8.x4.trans.shared.b16 {%0,%1,%2,%3}, [%4];"
                 : "=r"(r0), "=r"(r1), "=r"(r2), "=r"(r3) : "r"(addr));
}

// ---------------- operand conditioning ----------------
// 64x64-tile transpose, batched for the 4 DM x DM weights
__global__ void transpose64_b4_kernel(const float* __restrict__ w0, const float* __restrict__ w1,
                                      const float* __restrict__ w2, const float* __restrict__ w3,
                                      __half* __restrict__ o0, __half* __restrict__ o1,
                                      __half* __restrict__ o2, __half* __restrict__ o3)
{
    __shared__ float tile[64][65];
    const float* in = (blockIdx.z == 0) ? w0 : (blockIdx.z == 1) ? w1
                    : (blockIdx.z == 2) ? w2 : w3;
    __half* out = (blockIdx.z == 0) ? o0 : (blockIdx.z == 1) ? o1
                : (blockIdx.z == 2) ? o2 : o3;
    int n0 = blockIdx.x * 64, k0 = blockIdx.y * 64;
    int tx = threadIdx.x, ty = threadIdx.y;
#pragma unroll
    for (int i = ty; i < 64; i += 4)
        tile[i][tx] = in[(size_t)(k0 + i) * DM + n0 + tx];
    __syncthreads();
#pragma unroll
    for (int i = ty; i < 64; i += 4)
        out[(size_t)(n0 + i) * DM + k0 + tx] = __float2half_rn(tile[tx][i]);
}

// W1 ([DM][DFF] -> [DFF][DM]) and W2 ([DFF][DM] -> [DM][DFF]) in one launch.
// grid (64, 16, 2), block (64, 4).
__global__ void transpose64_w12_kernel(const float* __restrict__ W1, const float* __restrict__ W2,
                                       __half* __restrict__ o1, __half* __restrict__ o2)
{
    __shared__ float tile[64][65];
    const float* in; __half* out; int K, N, n0, k0;
    if (blockIdx.z == 0) { in = W1; out = o1; K = DM;  N = DFF; n0 = blockIdx.x * 64; k0 = blockIdx.y * 64; }
    else                 { in = W2; out = o2; K = DFF; N = DM;  n0 = blockIdx.y * 64; k0 = blockIdx.x * 64; }
    int tx = threadIdx.x, ty = threadIdx.y;
#pragma unroll
    for (int i = ty; i < 64; i += 4)
        tile[i][tx] = in[(size_t)(k0 + i) * N + n0 + tx];
    __syncthreads();
#pragma unroll
    for (int i = ty; i < 64; i += 4)
        out[(size_t)(n0 + i) * K + k0 + tx] = __float2half_rn(tile[tx][i]);
}

// ---------------- rope table build ----------------
__global__ void rope_table_kernel(float* __restrict__ cs, float* __restrict__ sn)
{
    int idx = blockIdx.x * blockDim.x + threadIdx.x;
    if (idx >= LL * 32) return;
    int i = idx & 31;
    int l = idx >> 5;
    double invf = pow(10000.0, -(double)i / 32.0);
    double ang = (double)l * invf;
    cs[idx] = (float)cos(ang);
    sn[idx] = (float)sin(ang);
}

// ---------------- LayerNorm (fp32 in, half out; optional x->half) ----------------
__global__ void ln_kernel(const float* __restrict__ x, const float* __restrict__ g,
                          const float* __restrict__ b, __half* __restrict__ y,
                          __half* __restrict__ xh_out)
{
    int row = blockIdx.x;
    int t = threadIdx.x;
    const float4* xr = (const float4*)(x + (size_t)row * DM);
    float4 v = xr[t];
    if (xh_out) {
        uint32_t lo = pack_h2(v.x, v.y), hi = pack_h2(v.z, v.w);
        ((uint2*)(xh_out + (size_t)row * DM))[t] = make_uint2(lo, hi);
    }
    float s  = v.x + v.y + v.z + v.w;
    float ss = v.x*v.x + v.y*v.y + v.z*v.z + v.w*v.w;
#pragma unroll
    for (int o = 16; o; o >>= 1) {
        s  += __shfl_xor_sync(0xffffffffu, s,  o);
        ss += __shfl_xor_sync(0xffffffffu, ss, o);
    }
    __shared__ float sh_s[8], sh_ss[8];
    int w = t >> 5, lane = t & 31;
    if (lane == 0) { sh_s[w] = s; sh_ss[w] = ss; }
    __syncthreads();
    if (t < 32) {
        s  = (t < 8) ? sh_s[t]  : 0.f;
        ss = (t < 8) ? sh_ss[t] : 0.f;
#pragma unroll
        for (int o = 4; o; o >>= 1) {
            s  += __shfl_xor_sync(0xffffffffu, s,  o);
            ss += __shfl_xor_sync(0xffffffffu, ss, o);
        }
        if (t == 0) { sh_s[0] = s; sh_ss[0] = ss; }
    }
    __syncthreads();
    float mu  = sh_s[0] * (1.f / DM);
    float var = sh_ss[0] * (1.f / DM) - mu * mu;
    float inv = rsqrtf(var + LN_EPS);
    float4 gv = ((const float4*)g)[t];
    float4 bv = ((const float4*)b)[t];
    uint32_t lo = pack_h2((v.x - mu) * inv * gv.x + bv.x,
                          (v.y - mu) * inv * gv.y + bv.y);
    uint32_t hi = pack_h2((v.z - mu) * inv * gv.z + bv.z,
                          (v.w - mu) * inv * gv.w + bv.w);
    ((uint2*)(y + (size_t)row * DM))[t] = make_uint2(lo, hi);
}

// ---------------- RoPE (heads < 8) + q scale, table-driven ----------------
__global__ void rope_h_kernel(__half* __restrict__ q, __half* __restrict__ k,
                              const float* __restrict__ cs_t, const float* __restrict__ sn_t)
{
    int idx = blockIdx.x * blockDim.x + threadIdx.x;
    const int total = NTOK * NH * (HD / 2);
    if (idx >= total) return;
    int i   = idx & 31;
    int h   = (idx >> 5) & 15;
    int tok = idx >> 9;
    int l   = tok & (LL - 1);
    size_t base = (size_t)tok * DM + h * HD + 2 * i;

    float q1 = __half2float(q[base]), q2 = __half2float(q[base + 1]);
    if (h < 8) {
        float cs = cs_t[l * 32 + i];
        float sn = sn_t[l * 32 + i];
        float k1 = __half2float(k[base]), k2 = __half2float(k[base + 1]);
        float qe = q1 * cs - q2 * sn;
        float qo = q1 * sn + q2 * cs;
        q1 = qe; q2 = qo;
        k[base]     = __float2half_rn(k1 * cs - k2 * sn);
        k[base + 1] = __float2half_rn(k1 * sn + k2 * cs);
    }
    q[base]     = __float2half_rn(q1 * 0.125f);
    q[base + 1] = __float2half_rn(q2 * 0.125f);
}

// ---------------- fp16 tensor-core GEMM (R13 exact) ----------------
#define AS_H 40
#define STAGE_H (128*AS_H*2)
#define HGEMM_SMEM (3*STAGE_H*2)

template<bool RELU, bool RES, bool HALF_OUT>
__global__ __launch_bounds__(128, 2)
void hgemm(const __half* __restrict__ A, const __half* __restrict__ Bt,
           const float* __restrict__ bias, const float* __restrict__ res,
           void* __restrict__ Cv, int M, int N, int K)
{
    extern __shared__ __half hsm[];
    int t = threadIdx.x;
    int wid = t >> 5, lane = t & 31;
    int g = lane >> 2, tq = lane & 3;
    int m0 = blockIdx.y * 128, n0 = blockIdx.x * 128;
    int wm = (wid >> 1) * 64;
    int wn = (wid & 1) * 64;

    float acc[4][8][4];
#pragma unroll
    for (int i = 0; i < 4; i++)
#pragma unroll
        for (int j = 0; j < 8; j++)
#pragma unroll
            for (int c = 0; c < 4; c++) acc[i][j][c] = 0.f;

    const int NK = K >> 5;

#pragma unroll
    for (int s = 0; s < 2; s++) {
        __half* as = hsm + s * STAGE_H;
        __half* bs = as + 128 * AS_H;
        int kb = s << 5;
#pragma unroll
        for (int u = 0; u < 4; u++) {
            int i = t + u * 128;
            int row = i >> 2, ch = i & 3;
            cp16(&as[row*AS_H + ch*8], A  + (size_t)(m0 + row) * K + kb + ch * 8);
            cp16(&bs[row*AS_H + ch*8], Bt + (size_t)(n0 + row) * K + kb + ch * 8);
        }
        CP_COMMIT();
    }

    for (int j = 0; j < NK; j++) {
        if (j + 2 < NK) { CP_WAIT1(); } else { CP_WAIT0(); }
        __syncthreads();

        int buf = j % 3;
        const uint32_t* as = (const uint32_t*)(hsm + buf * STAGE_H);
        const uint32_t* bs = as + 128 * (AS_H/2);

#pragma unroll
        for (int kf = 0; kf < 2; kf++) {
            uint32_t bf[8][2];
#pragma unroll
            for (int nf = 0; nf < 8; nf++) {
                bf[nf][0] = bs[(wn + nf*8 + g)*(AS_H/2) + kf*8 + tq];
                bf[nf][1] = bs[(wn + nf*8 + g)*(AS_H/2) + kf*8 + tq + 4];
            }
#pragma unroll
            for (int mf = 0; mf < 4; mf++) {
                int row = wm + mf * 16;
                uint32_t a0 = as[(row + g)    *(AS_H/2) + kf*8 + tq];
                uint32_t a1 = as[(row + g + 8)*(AS_H/2) + kf*8 + tq];
                uint32_t a2 = as[(row + g)    *(AS_H/2) + kf*8 + tq + 4];
                uint32_t a3 = as[(row + g + 8)*(AS_H/2) + kf*8 + tq + 4];
#pragma unroll
                for (int nf = 0; nf < 8; nf++)
                    mma16(acc[mf][nf][0], acc[mf][nf][1], acc[mf][nf][2], acc[mf][nf][3],
                          a0, a1, a2, a3, bf[nf][0], bf[nf][1]);
            }
        }

        if (j + 2 < NK) {
            int s = (j + 2) % 3;
            __half* asw = hsm + s * STAGE_H;
            __half* bsw = asw + 128 * AS_H;
            int kb = (j + 2) << 5;
#pragma unroll
            for (int u = 0; u < 4; u++) {
                int i = t + u * 128;
                int row = i >> 2, ch = i & 3;
                cp16(&asw[row*AS_H + ch*8], A  + (size_t)(m0 + row) * K + kb + ch * 8);
                cp16(&bsw[row*AS_H + ch*8], Bt + (size_t)(n0 + row) * K + kb + ch * 8);
            }
            CP_COMMIT();
        }
    }

#pragma unroll
    for (int mf = 0; mf < 4; mf++) {
#pragma unroll
        for (int nf = 0; nf < 8; nf++) {
            int r0 = m0 + wm + mf*16 + g;
            int r1 = r0 + 8;
            int cN = n0 + wn + nf*8 + 2*tq;
            float b0v = bias[cN], b1v = bias[cN + 1];
            float v0 = acc[mf][nf][0] + b0v;
            float v1 = acc[mf][nf][1] + b1v;
            float v2 = acc[mf][nf][2] + b0v;
            float v3 = acc[mf][nf][3] + b1v;
            if (RES) {
                v0 += res[(size_t)r0 * N + cN];     v1 += res[(size_t)r0 * N + cN + 1];
                v2 += res[(size_t)r1 * N + cN];     v3 += res[(size_t)r1 * N + cN + 1];
            }
            if (RELU) {
                v0 = fmaxf(v0, 0.f); v1 = fmaxf(v1, 0.f);
                v2 = fmaxf(v2, 0.f); v3 = fmaxf(v3, 0.f);
            }
            if (HALF_OUT) {
                __half* C = (__half*)Cv;
                *(uint32_t*)(C + (size_t)r0 * N + cN) = pack_h2(v0, v1);
                *(uint32_t*)(C + (size_t)r1 * N + cN) = pack_h2(v2, v3);
            } else {
                float* C = (float*)Cv;
                *(float2*)(C + (size_t)r0 * N + cN) = make_float2(v0, v1);
                *(float2*)(C + (size_t)r1 * N + cN) = make_float2(v2, v3);
            }
        }
    }
}

// ---------------- fp16 flash attention: 3-deep KV pipeline ----------------
#define HS 72
#define ATTN_SMEM ((64*HS + 6*64*HS)*2)   // Q + 3K + 3V = 64512 bytes

__global__ __launch_bounds__(128, 3)
void attn_kernel(const __half* __restrict__ q, const __half* __restrict__ k,
                 const __half* __restrict__ v, __half* __restrict__ o)
{
    extern __shared__ __half hsm[];
    __half* Qs = hsm;
    __half* Ks[3] = { hsm + 64*HS,   hsm + 2*64*HS, hsm + 3*64*HS };
    __half* Vs[3] = { hsm + 4*64*HS, hsm + 5*64*HS, hsm + 6*64*HS };

    int qt = blockIdx.x, h = blockIdx.y, b = blockIdx.z;
    int t = threadIdx.x;
    int wid = t >> 5, lane = t & 31;
    int g = lane >> 2, tq = lane & 3;
    int wq = wid * 16;

    const __half* qbh = q + ((size_t)b * LL + qt * 64) * DM + h * HD;
    const __half* kbh = k + (size_t)b * LL * DM + h * HD;
    const __half* vbh = v + (size_t)b * LL * DM + h * HD;

    const int NT = LL / 64;

    // prologue: group0 = Q + tile0; group1 = tile1
#pragma unroll
    for (int u = 0; u < 4; u++) {
        int i = t + u * 128;
        int rr = i >> 3, c8 = i & 7;
        cp16(&Qs[rr*HS + c8*8],    qbh + (size_t)rr * DM + c8 * 8);
        cp16(&Ks[0][rr*HS + c8*8], kbh + (size_t)rr * DM + c8 * 8);
        cp16(&Vs[0][rr*HS + c8*8], vbh + (size_t)rr * DM + c8 * 8);
    }
    CP_COMMIT();
#pragma unroll
    for (int u = 0; u < 4; u++) {
        int i = t + u * 128;
        int rr = i >> 3, c8 = i & 7;
        cp16(&Ks[1][rr*HS + c8*8], kbh + (size_t)(64 + rr) * DM + c8 * 8);
        cp16(&Vs[1][rr*HS + c8*8], vbh + (size_t)(64 + rr) * DM + c8 * 8);
    }
    CP_COMMIT();
    CP_WAIT1();   // Q + tile0 arrived
    __syncthreads();

    uint32_t qa[4][4];
    {
        const uint32_t* qs = (const uint32_t*)Qs;
#pragma unroll
        for (int kf = 0; kf < 4; kf++) {
            qa[kf][0] = qs[(wq + g)    *(HS/2) + kf*8 + tq];
            qa[kf][1] = qs[(wq + g + 8)*(HS/2) + kf*8 + tq];
            qa[kf][2] = qs[(wq + g)    *(HS/2) + kf*8 + tq + 4];
            qa[kf][3] = qs[(wq + g + 8)*(HS/2) + kf*8 + tq + 4];
        }
    }

    int row_off = ((lane >> 3) & 1) * 8 + (lane & 7);
    int col_off = (lane >> 4) * 8;

    float oacc[8][4];
#pragma unroll
    for (int i = 0; i < 8; i++)
#pragma unroll
        for (int c = 0; c < 4; c++) oacc[i][c] = 0.f;
    float m0 = -1e30f, m1 = -1e30f, l0 = 0.f, l1 = 0.f;

    for (int j = 0; j < NT; j++) {
        // wait for tile j (outstanding groups: {j} and possibly {j+1})
        if (j + 1 < NT) { CP_WAIT1(); } else { CP_WAIT0(); }
        __syncthreads();   // also protects buffer (j+2)%3 against compute j-1 readers

        // issue tile j+2 (distance-2 prefetch)
        if (j + 2 < NT) {
            int nb = (j + 2) % 3;
            const __half* kn = kbh + (size_t)(j + 2) * 64 * DM;
            const __half* vn = vbh + (size_t)(j + 2) * 64 * DM;
#pragma unroll
            for (int u = 0; u < 4; u++) {
                int i = t + u * 128;
                int rr = i >> 3, c8 = i & 7;
                cp16(&Ks[nb][rr*HS + c8*8], kn + (size_t)rr * DM + c8 * 8);
                cp16(&Vs[nb][rr*HS + c8*8], vn + (size_t)rr * DM + c8 * 8);
            }
            CP_COMMIT();
        }

        int cur = j % 3;
        const uint32_t* ks = (const uint32_t*)Ks[cur];
        float sacc[8][4];
#pragma unroll
        for (int i = 0; i < 8; i++)
#pragma unroll
            for (int c = 0; c < 4; c++) sacc[i][c] = 0.f;

#pragma unroll
        for (int kf = 0; kf < 4; kf++) {
#pragma unroll
            for (int nf = 0; nf < 8; nf++) {
                uint32_t b0 = ks[(nf*8 + g)*(HS/2) + kf*8 + tq];
                uint32_t b1 = ks[(nf*8 + g)*(HS/2) + kf*8 + tq + 4];
                mma16(sacc[nf][0], sacc[nf][1], sacc[nf][2], sacc[nf][3],
                      qa[kf][0], qa[kf][1], qa[kf][2], qa[kf][3], b0, b1);
            }
        }

        float mx0 = -1e30f, mx1 = -1e30f;
#pragma unroll
        for (int nf = 0; nf < 8; nf++) {
            mx0 = fmaxf(mx0, fmaxf(sacc[nf][0], sacc[nf][1]));
            mx1 = fmaxf(mx1, fmaxf(sacc[nf][2], sacc[nf][3]));
        }
        mx0 = fmaxf(mx0, __shfl_xor_sync(0xffffffffu, mx0, 1));
        mx0 = fmaxf(mx0, __shfl_xor_sync(0xffffffffu, mx0, 2));
        mx1 = fmaxf(mx1, __shfl_xor_sync(0xffffffffu, mx1, 1));
        mx1 = fmaxf(mx1, __shfl_xor_sync(0xffffffffu, mx1, 2));
        float mn0 = fmaxf(m0, mx0), mn1 = fmaxf(m1, mx1);
        float al0 = __expf(m0 - mn0), al1 = __expf(m1 - mn1);

        uint32_t pa[8][2];
        float sum0 = 0.f, sum1 = 0.f;
#pragma unroll
        for (int nf = 0; nf < 8; nf++) {
            float p0 = __expf(sacc[nf][0] - mn0);
            float p1 = __expf(sacc[nf][1] - mn0);
            float p2 = __expf(sacc[nf][2] - mn1);
            float p3 = __expf(sacc[nf][3] - mn1);
            sum0 += p0 + p1;
            sum1 += p2 + p3;
            pa[nf][0] = pack_h2(p0, p1);
            pa[nf][1] = pack_h2(p2, p3);
        }
        sum0 += __shfl_xor_sync(0xffffffffu, sum0, 1);
        sum0 += __shfl_xor_sync(0xffffffffu, sum0, 2);
        sum1 += __shfl_xor_sync(0xffffffffu, sum1, 1);
        sum1 += __shfl_xor_sync(0xffffffffu, sum1, 2);
        l0 = l0 * al0 + sum0;
        l1 = l1 * al1 + sum1;
        m0 = mn0; m1 = mn1;
#pragma unroll
        for (int nf = 0; nf < 8; nf++) {
            oacc[nf][0] *= al0; oacc[nf][1] *= al0;
            oacc[nf][2] *= al1; oacc[nf][3] *= al1;
        }

        uint32_t vs_base = (uint32_t)__cvta_generic_to_shared(Vs[cur]);
#pragma unroll
        for (int kf = 0; kf < 4; kf++) {
            uint32_t a0 = pa[2*kf][0],   a1 = pa[2*kf][1];
            uint32_t a2 = pa[2*kf+1][0], a3 = pa[2*kf+1][1];
#pragma unroll
            for (int np = 0; np < 4; np++) {
                uint32_t addr = vs_base +
                    (uint32_t)(((kf*16 + row_off)*HS + np*16 + col_off) * 2);
                uint32_t r0, r1, r2, r3;
                ldmx4t(r0, r1, r2, r3, addr);
                mma16(oacc[2*np][0],   oacc[2*np][1],   oacc[2*np][2],   oacc[2*np][3],
                      a0, a1, a2, a3, r0, r1);
                mma16(oacc[2*np+1][0], oacc[2*np+1][1], oacc[2*np+1][2], oacc[2*np+1][3],
                      a0, a1, a2, a3, r2, r3);
            }
        }
    }

    float inv0 = 1.f / l0, inv1 = 1.f / l1;
    size_t row0 = (size_t)b * LL + qt * 64 + wq + g;
    size_t row1 = row0 + 8;
#pragma unroll
    for (int nf = 0; nf < 8; nf++) {
        int cN = h * HD + nf*8 + 2*tq;
        *(uint32_t*)(o + row0 * DM + cN) = pack_h2(oacc[nf][0] * inv0, oacc[nf][1] * inv0);
        *(uint32_t*)(o + row1 * DM + cN) = pack_h2(oacc[nf][2] * inv1, oacc[nf][3] * inv1);
    }
}

// ---------------- launcher ----------------
extern "C" void kernel_launch(void* const* d_in, const int* in_sizes, int n_in,
                              void* d_out, int out_size)
{
    const float* x     = (const float*)d_in[0];
    const float* Wq    = (const float*)d_in[1];
    const float* bq    = (const float*)d_in[2];
    const float* Wk    = (const float*)d_in[3];
    const float* bk    = (const float*)d_in[4];
    const float* Wv    = (const float*)d_in[5];
    const float* bv    = (const float*)d_in[6];
    const float* Wo    = (const float*)d_in[7];
    const float* bo    = (const float*)d_in[8];
    const float* ln1_g = (const float*)d_in[9];
    const float* ln1_b = (const float*)d_in[10];
    const float* ln2_g = (const float*)d_in[11];
    const float* ln2_b = (const float*)d_in[12];
    const float* W1    = (const float*)d_in[13];
    const float* b1    = (const float*)d_in[14];
    const float* W2    = (const float*)d_in[15];
    const float* b2    = (const float*)d_in[16];
    float* out = (float*)d_out;

    float *x2, *cs_t, *sn_t;
    __half *xh, *xnh, *qh, *kh, *vh, *oh, *xn2h, *hbh;
    __half *wqh, *wkh, *wvh, *woh, *w1h, *w2h;
    cudaGetSymbolAddress((void**)&x2,   g_x2);
    cudaGetSymbolAddress((void**)&xh,   g_xh);
    cudaGetSymbolAddress((void**)&xnh,  g_xnh);
    cudaGetSymbolAddress((void**)&qh,   g_qh);
    cudaGetSymbolAddress((void**)&kh,   g_kh);
    cudaGetSymbolAddress((void**)&vh,   g_vh);
    cudaGetSymbolAddress((void**)&oh,   g_oh);
    cudaGetSymbolAddress((void**)&xn2h, g_xn2h);
    cudaGetSymbolAddress((void**)&hbh,  g_hbh);
    cudaGetSymbolAddress((void**)&wqh,  g_wqh);
    cudaGetSymbolAddress((void**)&wkh,  g_wkh);
    cudaGetSymbolAddress((void**)&wvh,  g_wvh);
    cudaGetSymbolAddress((void**)&woh,  g_woh);
    cudaGetSymbolAddress((void**)&w1h,  g_w1h);
    cudaGetSymbolAddress((void**)&w2h,  g_w2h);
    cudaGetSymbolAddress((void**)&cs_t, g_cs);
    cudaGetSymbolAddress((void**)&sn_t, g_sn);

    static bool attr_set = false;
    if (!attr_set) {
        cudaFuncSetAttribute((const void*)hgemm<false,false,true>, cudaFuncAttributeMaxDynamicSharedMemorySize, HGEMM_SMEM);
        cudaFuncSetAttribute((const void*)hgemm<false,true,false>, cudaFuncAttributeMaxDynamicSharedMemorySize, HGEMM_SMEM);
        cudaFuncSetAttribute((const void*)hgemm<true,false,true>,  cudaFuncAttributeMaxDynamicSharedMemorySize, HGEMM_SMEM);
        cudaFuncSetAttribute((const void*)attn_kernel, cudaFuncAttributeMaxDynamicSharedMemorySize, ATTN_SMEM);
        attr_set = true;
    }

    // conditioning: rope tables; weights -> transposed half [N][K]
    rope_table_kernel<<<(LL*32 + 255)/256, 256>>>(cs_t, sn_t);
    {
        dim3 bt(64, 4);
        transpose64_b4_kernel<<<dim3(DM/64, DM/64, 4), bt>>>(Wq, Wk, Wv, Wo,
                                                             wqh, wkh, wvh, woh);
        transpose64_w12_kernel<<<dim3(DFF/64, DM/64, 2), bt>>>(W1, W2, w1h, w2h);
    }

    // LN1 + x->half in one pass
    ln_kernel<<<NTOK, 256>>>(x, ln1_g, ln1_b, xnh, xh);

    dim3 g1(DM / 128, NTOK / 128);     // (8, 32)
    hgemm<false,false,true><<<g1, 128, HGEMM_SMEM>>>(xnh, wqh, bq, nullptr, qh, NTOK, DM, DM);
    hgemm<false,false,true><<<g1, 128, HGEMM_SMEM>>>(xh,  wkh, bk, nullptr, kh, NTOK, DM, DM);
    hgemm<false,false,true><<<g1, 128, HGEMM_SMEM>>>(xh,  wvh, bv, nullptr, vh, NTOK, DM, DM);

    const int pairs = NTOK * NH * (HD / 2);
    rope_h_kernel<<<(pairs + 255) / 256, 256>>>(qh, kh, cs_t, sn_t);

    dim3 ga(LL / 64, NH, BB);
    attn_kernel<<<ga, 128, ATTN_SMEM>>>(qh, kh, vh, oh);

    hgemm<false,true,false><<<g1, 128, HGEMM_SMEM>>>(oh, woh, bo, x, x2, NTOK, DM, DM);

    ln_kernel<<<NTOK, 256>>>(x2, ln2_g, ln2_b, xn2h, nullptr);

    dim3 g2(DFF / 128, NTOK / 128);    // (32, 32)
    hgemm<true,false,true><<<g2, 128, HGEMM_SMEM>>>(xn2h, w1h, b1, nullptr, hbh, NTOK, DFF, DM);
    hgemm<false,true,false><<<g1, 128, HGEMM_SMEM>>>(hbh, w2h, b2, x2, out, NTOK, DM, DFF);
}

// round 15
// speedup vs baseline: 1.0261x; 1.0261x over previous
#include <cuda_runtime.h>
#include <cuda_fp16.h>
#include <math.h>
#include <stdint.h>

#define BB 2
#define LL 2048
#define DM 1024
#define NH 16
#define HD 64
#define DFF 4096
#define NTOK (BB*LL)
#define LN_EPS 1e-5f

// ---------------- scratch (no allocation allowed) ----------------
__device__ float  g_x2 [NTOK*DM];
__device__ __half g_xh [NTOK*DM];
__device__ __half g_xnh[NTOK*DM];
__device__ __half g_qh [NTOK*DM];
__device__ __half g_kh [NTOK*DM];
__device__ __half g_vh [NTOK*DM];
__device__ __half g_oh [NTOK*DM];
__device__ __half g_xn2h[NTOK*DM];
__device__ __half g_hbh[NTOK*DFF];
// transposed half weights [N][K]
__device__ __half g_wqh[DM*DM];
__device__ __half g_wkh[DM*DM];
__device__ __half g_wvh[DM*DM];
__device__ __half g_woh[DM*DM];
__device__ __half g_w1h[DFF*DM];
__device__ __half g_w2h[DM*DFF];
// rope tables
__device__ float g_cs[LL*32];
__device__ float g_sn[LL*32];

// ---------------- helpers ----------------
__device__ __forceinline__ void cp16(void* smem, const void* g) {
    unsigned sa = (unsigned)__cvta_generic_to_shared(smem);
    asm volatile("cp.async.cg.shared.global [%0], [%1], 16;" :: "r"(sa), "l"(g));
}
#define CP_COMMIT() asm volatile("cp.async.commit_group;" ::: "memory")
#define CP_WAIT0()  asm volatile("cp.async.wait_group 0;" ::: "memory")
#define CP_WAIT1()  asm volatile("cp.async.wait_group 1;" ::: "memory")

__device__ __forceinline__ void mma16(float& c0, float& c1, float& c2, float& c3,
                                      uint32_t a0, uint32_t a1, uint32_t a2, uint32_t a3,
                                      uint32_t b0, uint32_t b1) {
    asm("mma.sync.aligned.m16n8k16.row.col.f32.f16.f16.f32 "
        "{%0,%1,%2,%3},{%4,%5,%6,%7},{%8,%9},{%0,%1,%2,%3};"
        : "+f"(c0), "+f"(c1), "+f"(c2), "+f"(c3)
        : "r"(a0), "r"(a1), "r"(a2), "r"(a3), "r"(b0), "r"(b1));
}
__device__ __forceinline__ uint32_t pack_h2(float x, float y) {
    uint32_t r;
    asm("cvt.rn.f16x2.f32 %0, %1, %2;" : "=r"(r) : "f"(y), "f"(x));
    return r;
}
__device__ __forceinline__ void ldmx4t(uint32_t& r0, uint32_t& r1, uint32_t& r2, uint32_t& r3,
                                       uint32_t addr) {
    asm volatile("ldmatrix.sync.aligned.m8n8.x4.trans.shared.b16 {%0,%1,%2,%3}, [%4];"
                 : "=r"(r0), "=r"(r1), "=r"(r2), "=r"(r3) : "r"(addr));
}

// ---------------- operand conditioning ----------------
__global__ void f2h_kernel(const float* __restrict__ in, __half* __restrict__ out, int n4)
{
    int i = blockIdx.x * blockDim.x + threadIdx.x;
    if (i >= n4) return;
    float4 v = ((const float4*)in)[i];
    uint32_t lo = pack_h2(v.x, v.y), hi = pack_h2(v.z, v.w);
    ((uint2*)out)[i] = make_uint2(lo, hi);
}

// 64x64-tile transpose, batched for the 4 DM x DM weights
__global__ void transpose64_b4_kernel(const float* __restrict__ w0, const float* __restrict__ w1,
                                      const float* __restrict__ w2, const float* __restrict__ w3,
                                      __half* __restrict__ o0, __half* __restrict__ o1,
                                      __half* __restrict__ o2, __half* __restrict__ o3)
{
    __shared__ float tile[64][65];
    const float* in = (blockIdx.z == 0) ? w0 : (blockIdx.z == 1) ? w1
                    : (blockIdx.z == 2) ? w2 : w3;
    __half* out = (blockIdx.z == 0) ? o0 : (blockIdx.z == 1) ? o1
                : (blockIdx.z == 2) ? o2 : o3;
    int n0 = blockIdx.x * 64, k0 = blockIdx.y * 64;
    int tx = threadIdx.x, ty = threadIdx.y;
#pragma unroll
    for (int i = ty; i < 64; i += 4)
        tile[i][tx] = in[(size_t)(k0 + i) * DM + n0 + tx];
    __syncthreads();
#pragma unroll
    for (int i = ty; i < 64; i += 4)
        out[(size_t)(n0 + i) * DM + k0 + tx] = __float2half_rn(tile[tx][i]);
}

// W1 ([DM][DFF] -> [DFF][DM]) and W2 ([DFF][DM] -> [DM][DFF]) in one launch.
// grid (64, 16, 2), block (64, 4).
__global__ void transpose64_w12_kernel(const float* __restrict__ W1, const float* __restrict__ W2,
                                       __half* __restrict__ o1, __half* __restrict__ o2)
{
    __shared__ float tile[64][65];
    const float* in; __half* out; int K, N, n0, k0;
    if (blockIdx.z == 0) { in = W1; out = o1; K = DM;  N = DFF; n0 = blockIdx.x * 64; k0 = blockIdx.y * 64; }
    else                 { in = W2; out = o2; K = DFF; N = DM;  n0 = blockIdx.y * 64; k0 = blockIdx.x * 64; }
    int tx = threadIdx.x, ty = threadIdx.y;
#pragma unroll
    for (int i = ty; i < 64; i += 4)
        tile[i][tx] = in[(size_t)(k0 + i) * N + n0 + tx];
    __syncthreads();
#pragma unroll
    for (int i = ty; i < 64; i += 4)
        out[(size_t)(n0 + i) * K + k0 + tx] = __float2half_rn(tile[tx][i]);
}

// ---------------- rope table build ----------------
__global__ void rope_table_kernel(float* __restrict__ cs, float* __restrict__ sn)
{
    int idx = blockIdx.x * blockDim.x + threadIdx.x;
    if (idx >= LL * 32) return;
    int i = idx & 31;
    int l = idx >> 5;
    double invf = pow(10000.0, -(double)i / 32.0);
    double ang = (double)l * invf;
    cs[idx] = (float)cos(ang);
    sn[idx] = (float)sin(ang);
}

// ---------------- LayerNorm (fp32 in, half out) ----------------
__global__ void ln_kernel(const float* __restrict__ x, const float* __restrict__ g,
                          const float* __restrict__ b, __half* __restrict__ y)
{
    int row = blockIdx.x;
    int t = threadIdx.x;
    const float4* xr = (const float4*)(x + (size_t)row * DM);
    float4 v = xr[t];
    float s  = v.x + v.y + v.z + v.w;
    float ss = v.x*v.x + v.y*v.y + v.z*v.z + v.w*v.w;
#pragma unroll
    for (int o = 16; o; o >>= 1) {
        s  += __shfl_xor_sync(0xffffffffu, s,  o);
        ss += __shfl_xor_sync(0xffffffffu, ss, o);
    }
    __shared__ float sh_s[8], sh_ss[8];
    int w = t >> 5, lane = t & 31;
    if (lane == 0) { sh_s[w] = s; sh_ss[w] = ss; }
    __syncthreads();
    if (t < 32) {
        s  = (t < 8) ? sh_s[t]  : 0.f;
        ss = (t < 8) ? sh_ss[t] : 0.f;
#pragma unroll
        for (int o = 4; o; o >>= 1) {
            s  += __shfl_xor_sync(0xffffffffu, s,  o);
            ss += __shfl_xor_sync(0xffffffffu, ss, o);
        }
        if (t == 0) { sh_s[0] = s; sh_ss[0] = ss; }
    }
    __syncthreads();
    float mu  = sh_s[0] * (1.f / DM);
    float var = sh_ss[0] * (1.f / DM) - mu * mu;
    float inv = rsqrtf(var + LN_EPS);
    float4 gv = ((const float4*)g)[t];
    float4 bv = ((const float4*)b)[t];
    uint32_t lo = pack_h2((v.x - mu) * inv * gv.x + bv.x,
                          (v.y - mu) * inv * gv.y + bv.y);
    uint32_t hi = pack_h2((v.z - mu) * inv * gv.z + bv.z,
                          (v.w - mu) * inv * gv.w + bv.w);
    ((uint2*)(y + (size_t)row * DM))[t] = make_uint2(lo, hi);
}

// ---------------- RoPE (heads < 8) + q scale, table-driven ----------------
__global__ void rope_h_kernel(__half* __restrict__ q, __half* __restrict__ k,
                              const float* __restrict__ cs_t, const float* __restrict__ sn_t)
{
    int idx = blockIdx.x * blockDim.x + threadIdx.x;
    const int total = NTOK * NH * (HD / 2);
    if (idx >= total) return;
    int i   = idx & 31;
    int h   = (idx >> 5) & 15;
    int tok = idx >> 9;
    int l   = tok & (LL - 1);
    size_t base = (size_t)tok * DM + h * HD + 2 * i;

    float q1 = __half2float(q[base]), q2 = __half2float(q[base + 1]);
    if (h < 8) {
        float cs = cs_t[l * 32 + i];
        float sn = sn_t[l * 32 + i];
        float k1 = __half2float(k[base]), k2 = __half2float(k[base + 1]);
        float qe = q1 * cs - q2 * sn;
        float qo = q1 * sn + q2 * cs;
        q1 = qe; q2 = qo;
        k[base]     = __float2half_rn(k1 * cs - k2 * sn);
        k[base + 1] = __float2half_rn(k1 * sn + k2 * cs);
    }
    q[base]     = __float2half_rn(q1 * 0.125f);
    q[base + 1] = __float2half_rn(q2 * 0.125f);
}

// ---------------- fp16 tensor-core GEMM (R13 exact) ----------------
#define AS_H 40
#define STAGE_H (128*AS_H*2)
#define HGEMM_SMEM (3*STAGE_H*2)

template<bool RELU, bool RES, bool HALF_OUT>
__global__ __launch_bounds__(128, 2)
void hgemm(const __half* __restrict__ A, const __half* __restrict__ Bt,
           const float* __restrict__ bias, const float* __restrict__ res,
           void* __restrict__ Cv, int M, int N, int K)
{
    extern __shared__ __half hsm[];
    int t = threadIdx.x;
    int wid = t >> 5, lane = t & 31;
    int g = lane >> 2, tq = lane & 3;
    int m0 = blockIdx.y * 128, n0 = blockIdx.x * 128;
    int wm = (wid >> 1) * 64;
    int wn = (wid & 1) * 64;

    float acc[4][8][4];
#pragma unroll
    for (int i = 0; i < 4; i++)
#pragma unroll
        for (int j = 0; j < 8; j++)
#pragma unroll
            for (int c = 0; c < 4; c++) acc[i][j][c] = 0.f;

    const int NK = K >> 5;

#pragma unroll
    for (int s = 0; s < 2; s++) {
        __half* as = hsm + s * STAGE_H;
        __half* bs = as + 128 * AS_H;
        int kb = s << 5;
#pragma unroll
        for (int u = 0; u < 4; u++) {
            int i = t + u * 128;
            int row = i >> 2, ch = i & 3;
            cp16(&as[row*AS_H + ch*8], A  + (size_t)(m0 + row) * K + kb + ch * 8);
            cp16(&bs[row*AS_H + ch*8], Bt + (size_t)(n0 + row) * K + kb + ch * 8);
        }
        CP_COMMIT();
    }

    for (int j = 0; j < NK; j++) {
        if (j + 2 < NK) { CP_WAIT1(); } else { CP_WAIT0(); }
        __syncthreads();

        int buf = j % 3;
        const uint32_t* as = (const uint32_t*)(hsm + buf * STAGE_H);
        const uint32_t* bs = as + 128 * (AS_H/2);

#pragma unroll
        for (int kf = 0; kf < 2; kf++) {
            uint32_t bf[8][2];
#pragma unroll
            for (int nf = 0; nf < 8; nf++) {
                bf[nf][0] = bs[(wn + nf*8 + g)*(AS_H/2) + kf*8 + tq];
                bf[nf][1] = bs[(wn + nf*8 + g)*(AS_H/2) + kf*8 + tq + 4];
            }
#pragma unroll
            for (int mf = 0; mf < 4; mf++) {
                int row = wm + mf * 16;
                uint32_t a0 = as[(row + g)    *(AS_H/2) + kf*8 + tq];
                uint32_t a1 = as[(row + g + 8)*(AS_H/2) + kf*8 + tq];
                uint32_t a2 = as[(row + g)    *(AS_H/2) + kf*8 + tq + 4];
                uint32_t a3 = as[(row + g + 8)*(AS_H/2) + kf*8 + tq + 4];
#pragma unroll
                for (int nf = 0; nf < 8; nf++)
                    mma16(acc[mf][nf][0], acc[mf][nf][1], acc[mf][nf][2], acc[mf][nf][3],
                          a0, a1, a2, a3, bf[nf][0], bf[nf][1]);
            }
        }

        if (j + 2 < NK) {
            int s = (j + 2) % 3;
            __half* asw = hsm + s * STAGE_H;
            __half* bsw = asw + 128 * AS_H;
            int kb = (j + 2) << 5;
#pragma unroll
            for (int u = 0; u < 4; u++) {
                int i = t + u * 128;
                int row = i >> 2, ch = i & 3;
                cp16(&asw[row*AS_H + ch*8], A  + (size_t)(m0 + row) * K + kb + ch * 8);
                cp16(&bsw[row*AS_H + ch*8], Bt + (size_t)(n0 + row) * K + kb + ch * 8);
            }
            CP_COMMIT();
        }
    }

#pragma unroll
    for (int mf = 0; mf < 4; mf++) {
#pragma unroll
        for (int nf = 0; nf < 8; nf++) {
            int r0 = m0 + wm + mf*16 + g;
            int r1 = r0 + 8;
            int cN = n0 + wn + nf*8 + 2*tq;
            float b0v = bias[cN], b1v = bias[cN + 1];
            float v0 = acc[mf][nf][0] + b0v;
            float v1 = acc[mf][nf][1] + b1v;
            float v2 = acc[mf][nf][2] + b0v;
            float v3 = acc[mf][nf][3] + b1v;
            if (RES) {
                v0 += res[(size_t)r0 * N + cN];     v1 += res[(size_t)r0 * N + cN + 1];
                v2 += res[(size_t)r1 * N + cN];     v3 += res[(size_t)r1 * N + cN + 1];
            }
            if (RELU) {
                v0 = fmaxf(v0, 0.f); v1 = fmaxf(v1, 0.f);
                v2 = fmaxf(v2, 0.f); v3 = fmaxf(v3, 0.f);
            }
            if (HALF_OUT) {
                __half* C = (__half*)Cv;
                *(uint32_t*)(C + (size_t)r0 * N + cN) = pack_h2(v0, v1);
                *(uint32_t*)(C + (size_t)r1 * N + cN) = pack_h2(v2, v3);
            } else {
                float* C = (float*)Cv;
                *(float2*)(C + (size_t)r0 * N + cN) = make_float2(v0, v1);
                *(float2*)(C + (size_t)r1 * N + cN) = make_float2(v2, v3);
            }
        }
    }
}

// ---------------- fp16 flash attention (R13 exact: static smem, depth-2, occ 3) ----------------
#define HS 72

__global__ __launch_bounds__(128, 3)
void attn_kernel(const __half* __restrict__ q, const __half* __restrict__ k,
                 const __half* __restrict__ v, __half* __restrict__ o)
{
    __shared__ __half Qs[64*HS];
    __shared__ __half Ks[2][64*HS];
    __shared__ __half Vs[2][64*HS];

    int qt = blockIdx.x, h = blockIdx.y, b = blockIdx.z;
    int t = threadIdx.x;
    int wid = t >> 5, lane = t & 31;
    int g = lane >> 2, tq = lane & 3;
    int wq = wid * 16;

    const __half* qbh = q + ((size_t)b * LL + qt * 64) * DM + h * HD;
    const __half* kbh = k + (size_t)b * LL * DM + h * HD;
    const __half* vbh = v + (size_t)b * LL * DM + h * HD;

#pragma unroll
    for (int u = 0; u < 4; u++) {
        int i = t + u * 128;
        int rr = i >> 3, c8 = i & 7;
        cp16(&Qs[rr*HS + c8*8],    qbh + (size_t)rr * DM + c8 * 8);
        cp16(&Ks[0][rr*HS + c8*8], kbh + (size_t)rr * DM + c8 * 8);
        cp16(&Vs[0][rr*HS + c8*8], vbh + (size_t)rr * DM + c8 * 8);
    }
    CP_COMMIT(); CP_WAIT0(); __syncthreads();

    uint32_t qa[4][4];
    {
        const uint32_t* qs = (const uint32_t*)Qs;
#pragma unroll
        for (int kf = 0; kf < 4; kf++) {
            qa[kf][0] = qs[(wq + g)    *(HS/2) + kf*8 + tq];
            qa[kf][1] = qs[(wq + g + 8)*(HS/2) + kf*8 + tq];
            qa[kf][2] = qs[(wq + g)    *(HS/2) + kf*8 + tq + 4];
            qa[kf][3] = qs[(wq + g + 8)*(HS/2) + kf*8 + tq + 4];
        }
    }

    int row_off = ((lane >> 3) & 1) * 8 + (lane & 7);
    int col_off = (lane >> 4) * 8;

    float oacc[8][4];
#pragma unroll
    for (int i = 0; i < 8; i++)
#pragma unroll
        for (int c = 0; c < 4; c++) oacc[i][c] = 0.f;
    float m0 = -1e30f, m1 = -1e30f, l0 = 0.f, l1 = 0.f;

    for (int j = 0; j < LL/64; j++) {
        int cur = j & 1;
        if (j + 1 < LL/64) {
            int nxt = cur ^ 1;
            const __half* kn = kbh + (size_t)(j + 1) * 64 * DM;
            const __half* vn = vbh + (size_t)(j + 1) * 64 * DM;
#pragma unroll
            for (int u = 0; u < 4; u++) {
                int i = t + u * 128;
                int rr = i >> 3, c8 = i & 7;
                cp16(&Ks[nxt][rr*HS + c8*8], kn + (size_t)rr * DM + c8 * 8);
                cp16(&Vs[nxt][rr*HS + c8*8], vn + (size_t)rr * DM + c8 * 8);
            }
        }
        CP_COMMIT();

        const uint32_t* ks = (const uint32_t*)Ks[cur];
        float sacc[8][4];
#pragma unroll
        for (int i = 0; i < 8; i++)
#pragma unroll
            for (int c = 0; c < 4; c++) sacc[i][c] = 0.f;

#pragma unroll
        for (int kf = 0; kf < 4; kf++) {
#pragma unroll
            for (int nf = 0; nf < 8; nf++) {
                uint32_t b0 = ks[(nf*8 + g)*(HS/2) + kf*8 + tq];
                uint32_t b1 = ks[(nf*8 + g)*(HS/2) + kf*8 + tq + 4];
                mma16(sacc[nf][0], sacc[nf][1], sacc[nf][2], sacc[nf][3],
                      qa[kf][0], qa[kf][1], qa[kf][2], qa[kf][3], b0, b1);
            }
        }

        float mx0 = -1e30f, mx1 = -1e30f;
#pragma unroll
        for (int nf = 0; nf < 8; nf++) {
            mx0 = fmaxf(mx0, fmaxf(sacc[nf][0], sacc[nf][1]));
            mx1 = fmaxf(mx1, fmaxf(sacc[nf][2], sacc[nf][3]));
        }
        mx0 = fmaxf(mx0, __shfl_xor_sync(0xffffffffu, mx0, 1));
        mx0 = fmaxf(mx0, __shfl_xor_sync(0xffffffffu, mx0, 2));
        mx1 = fmaxf(mx1, __shfl_xor_sync(0xffffffffu, mx1, 1));
        mx1 = fmaxf(mx1, __shfl_xor_sync(0xffffffffu, mx1, 2));
        float mn0 = fmaxf(m0, mx0), mn1 = fmaxf(m1, mx1);
        float al0 = __expf(m0 - mn0), al1 = __expf(m1 - mn1);

        uint32_t pa[8][2];
        float sum0 = 0.f, sum1 = 0.f;
#pragma unroll
        for (int nf = 0; nf < 8; nf++) {
            float p0 = __expf(sacc[nf][0] - mn0);
            float p1 = __expf(sacc[nf][1] - mn0);
            float p2 = __expf(sacc[nf][2] - mn1);
            float p3 = __expf(sacc[nf][3] - mn1);
            sum0 += p0 + p1;
            sum1 += p2 + p3;
            pa[nf][0] = pack_h2(p0, p1);
            pa[nf][1] = pack_h2(p2, p3);
        }
        sum0 += __shfl_xor_sync(0xffffffffu, sum0, 1);
        sum0 += __shfl_xor_sync(0xffffffffu, sum0, 2);
        sum1 += __shfl_xor_sync(0xffffffffu, sum1, 1);
        sum1 += __shfl_xor_sync(0xffffffffu, sum1, 2);
        l0 = l0 * al0 + sum0;
        l1 = l1 * al1 + sum1;
        m0 = mn0; m1 = mn1;
#pragma unroll
        for (int nf = 0; nf < 8; nf++) {
            oacc[nf][0] *= al0; oacc[nf][1] *= al0;
            oacc[nf][2] *= al1; oacc[nf][3] *= al1;
        }

        uint32_t vs_base = (uint32_t)__cvta_generic_to_shared(&Vs[cur][0]);
#pragma unroll
        for (int kf = 0; kf < 4; kf++) {
            uint32_t a0 = pa[2*kf][0],   a1 = pa[2*kf][1];
            uint32_t a2 = pa[2*kf+1][0], a3 = pa[2*kf+1][1];
#pragma unroll
            for (int np = 0; np < 4; np++) {
                uint32_t addr = vs_base +
                    (uint32_t)(((kf*16 + row_off)*HS + np*16 + col_off) * 2);
                uint32_t r0, r1, r2, r3;
                ldmx4t(r0, r1, r2, r3, addr);
                mma16(oacc[2*np][0],   oacc[2*np][1],   oacc[2*np][2],   oacc[2*np][3],
                      a0, a1, a2, a3, r0, r1);
                mma16(oacc[2*np+1][0], oacc[2*np+1][1], oacc[2*np+1][2], oacc[2*np+1][3],
                      a0, a1, a2, a3, r2, r3);
            }
        }

        CP_WAIT0();
        __syncthreads();
    }

    float inv0 = 1.f / l0, inv1 = 1.f / l1;
    size_t row0 = (size_t)b * LL + qt * 64 + wq + g;
    size_t row1 = row0 + 8;
#pragma unroll
    for (int nf = 0; nf < 8; nf++) {
        int cN = h * HD + nf*8 + 2*tq;
        *(uint32_t*)(o + row0 * DM + cN) = pack_h2(oacc[nf][0] * inv0, oacc[nf][1] * inv0);
        *(uint32_t*)(o + row1 * DM + cN) = pack_h2(oacc[nf][2] * inv1, oacc[nf][3] * inv1);
    }
}

// ---------------- launcher ----------------
extern "C" void kernel_launch(void* const* d_in, const int* in_sizes, int n_in,
                              void* d_out, int out_size)
{
    const float* x     = (const float*)d_in[0];
    const float* Wq    = (const float*)d_in[1];
    const float* bq    = (const float*)d_in[2];
    const float* Wk    = (const float*)d_in[3];
    const float* bk    = (const float*)d_in[4];
    const float* Wv    = (const float*)d_in[5];
    const float* bv    = (const float*)d_in[6];
    const float* Wo    = (const float*)d_in[7];
    const float* bo    = (const float*)d_in[8];
    const float* ln1_g = (const float*)d_in[9];
    const float* ln1_b = (const float*)d_in[10];
    const float* ln2_g = (const float*)d_in[11];
    const float* ln2_b = (const float*)d_in[12];
    const float* W1    = (const float*)d_in[13];
    const float* b1    = (const float*)d_in[14];
    const float* W2    = (const float*)d_in[15];
    const float* b2    = (const float*)d_in[16];
    float* out = (float*)d_out;

    float *x2, *cs_t, *sn_t;
    __half *xh, *xnh, *qh, *kh, *vh, *oh, *xn2h, *hbh;
    __half *wqh, *wkh, *wvh, *woh, *w1h, *w2h;
    cudaGetSymbolAddress((void**)&x2,   g_x2);
    cudaGetSymbolAddress((void**)&xh,   g_xh);
    cudaGetSymbolAddress((void**)&xnh,  g_xnh);
    cudaGetSymbolAddress((void**)&qh,   g_qh);
    cudaGetSymbolAddress((void**)&kh,   g_kh);
    cudaGetSymbolAddress((void**)&vh,   g_vh);
    cudaGetSymbolAddress((void**)&oh,   g_oh);
    cudaGetSymbolAddress((void**)&xn2h, g_xn2h);
    cudaGetSymbolAddress((void**)&hbh,  g_hbh);
    cudaGetSymbolAddress((void**)&wqh,  g_wqh);
    cudaGetSymbolAddress((void**)&wkh,  g_wkh);
    cudaGetSymbolAddress((void**)&wvh,  g_wvh);
    cudaGetSymbolAddress((void**)&woh,  g_woh);
    cudaGetSymbolAddress((void**)&w1h,  g_w1h);
    cudaGetSymbolAddress((void**)&w2h,  g_w2h);
    cudaGetSymbolAddress((void**)&cs_t, g_cs);
    cudaGetSymbolAddress((void**)&sn_t, g_sn);

    static bool attr_set = false;
    if (!attr_set) {
        cudaFuncSetAttribute((const void*)hgemm<false,false,true>, cudaFuncAttributeMaxDynamicSharedMemorySize, HGEMM_SMEM);
        cudaFuncSetAttribute((const void*)hgemm<false,true,false>, cudaFuncAttributeMaxDynamicSharedMemorySize, HGEMM_SMEM);
        cudaFuncSetAttribute((const void*)hgemm<true,false,true>,  cudaFuncAttributeMaxDynamicSharedMemorySize, HGEMM_SMEM);
        attr_set = true;
    }

    // conditioning: x -> half; rope tables; weights -> transposed half [N][K]
    f2h_kernel<<<(NTOK*DM/4 + 255)/256, 256>>>(x, xh, NTOK*DM/4);
    rope_table_kernel<<<(LL*32 + 255)/256, 256>>>(cs_t, sn_t);
    {
        dim3 bt(64, 4);
        transpose64_b4_kernel<<<dim3(DM/64, DM/64, 4), bt>>>(Wq, Wk, Wv, Wo,
                                                             wqh, wkh, wvh, woh);
        transpose64_w12_kernel<<<dim3(DFF/64, DM/64, 2), bt>>>(W1, W2, w1h, w2h);
    }

    ln_kernel<<<NTOK, 256>>>(x, ln1_g, ln1_b, xnh);

    dim3 g1(DM / 128, NTOK / 128);     // (8, 32)
    hgemm<false,false,true><<<g1, 128, HGEMM_SMEM>>>(xnh, wqh, bq, nullptr, qh, NTOK, DM, DM);
    hgemm<false,false,true><<<g1, 128, HGEMM_SMEM>>>(xh,  wkh, bk, nullptr, kh, NTOK, DM, DM);
    hgemm<false,false,true><<<g1, 128, HGEMM_SMEM>>>(xh,  wvh, bv, nullptr, vh, NTOK, DM, DM);

    const int pairs = NTOK * NH * (HD / 2);
    rope_h_kernel<<<(pairs + 255) / 256, 256>>>(qh, kh, cs_t, sn_t);

    dim3 ga(LL / 64, NH, BB);
    attn_kernel<<<ga, 128>>>(qh, kh, vh, oh);

    hgemm<false,true,false><<<g1, 128, HGEMM_SMEM>>>(oh, woh, bo, x, x2, NTOK, DM, DM);

    ln_kernel<<<NTOK, 256>>>(x2, ln2_g, ln2_b, xn2h);

    dim3 g2(DFF / 128, NTOK / 128);    // (32, 32)
    hgemm<true,false,true><<<g2, 128, HGEMM_SMEM>>>(xn2h, w1h, b1, nullptr, hbh, NTOK, DFF, DM);
    hgemm<false,true,false><<<g1, 128, HGEMM_SMEM>>>(hbh, w2h, b2, x2, out, NTOK, DM, DFF);
}

// round 16
// speedup vs baseline: 1.0604x; 1.0334x over previous
#include <cuda_runtime.h>
#include <cuda_fp16.h>
#include <math.h>
#include <stdint.h>

#define BB 2
#define LL 2048
#define DM 1024
#define NH 16
#define HD 64
#define DFF 4096
#define NTOK (BB*LL)
#define LN_EPS 1e-5f

// ---------------- scratch (no allocation allowed) ----------------
__device__ float  g_x2 [NTOK*DM];
__device__ __half g_xh [NTOK*DM];
__device__ __half g_xnh[NTOK*DM];
__device__ __half g_qh [NTOK*DM];
__device__ __half g_kh [NTOK*DM];
__device__ __half g_vh [NTOK*DM];
__device__ __half g_oh [NTOK*DM];
__device__ __half g_xn2h[NTOK*DM];
__device__ __half g_hbh[NTOK*DFF];
// transposed half weights [N][K]
__device__ __half g_wqh[DM*DM];
__device__ __half g_wkh[DM*DM];
__device__ __half g_wvh[DM*DM];
__device__ __half g_woh[DM*DM];
__device__ __half g_w1h[DFF*DM];
__device__ __half g_w2h[DM*DFF];
// rope tables
__device__ float g_cs[LL*32];
__device__ float g_sn[LL*32];

// ---------------- helpers ----------------
__device__ __forceinline__ void cp16(void* smem, const void* g) {
    unsigned sa = (unsigned)__cvta_generic_to_shared(smem);
    asm volatile("cp.async.cg.shared.global [%0], [%1], 16;" :: "r"(sa), "l"(g));
}
#define CP_COMMIT() asm volatile("cp.async.commit_group;" ::: "memory")
#define CP_WAIT0()  asm volatile("cp.async.wait_group 0;" ::: "memory")
#define CP_WAIT1()  asm volatile("cp.async.wait_group 1;" ::: "memory")

__device__ __forceinline__ void mma16(float& c0, float& c1, float& c2, float& c3,
                                      uint32_t a0, uint32_t a1, uint32_t a2, uint32_t a3,
                                      uint32_t b0, uint32_t b1) {
    asm("mma.sync.aligned.m16n8k16.row.col.f32.f16.f16.f32 "
        "{%0,%1,%2,%3},{%4,%5,%6,%7},{%8,%9},{%0,%1,%2,%3};"
        : "+f"(c0), "+f"(c1), "+f"(c2), "+f"(c3)
        : "r"(a0), "r"(a1), "r"(a2), "r"(a3), "r"(b0), "r"(b1));
}
__device__ __forceinline__ uint32_t pack_h2(float x, float y) {
    uint32_t r;
    asm("cvt.rn.f16x2.f32 %0, %1, %2;" : "=r"(r) : "f"(y), "f"(x));
    return r;
}
__device__ __forceinline__ void ldmx4t(uint32_t& r0, uint32_t& r1, uint32_t& r2, uint32_t& r3,
                                       uint32_t addr) {
    asm volatile("ldmatrix.sync.aligned.m8n8.x4.trans.shared.b16 {%0,%1,%2,%3}, [%4];"
                 : "=r"(r0), "=r"(r1), "=r"(r2), "=r"(r3) : "r"(addr));
}

// ---------------- operand conditioning ----------------
__global__ void f2h_kernel(const float* __restrict__ in, __half* __restrict__ out, int n4)
{
    int i = blockIdx.x * blockDim.x + threadIdx.x;
    if (i >= n4) return;
    float4 v = ((const float4*)in)[i];
    uint32_t lo = pack_h2(v.x, v.y), hi = pack_h2(v.z, v.w);
    ((uint2*)out)[i] = make_uint2(lo, hi);
}

// All six weight transposes in one launch, vectorized.
// z = 0..3: Wq/Wk/Wv/Wo  ([DM][DM] -> [DM][DM]),  grid x limited to 16
// z = 4:    W1 ([DM][DFF] -> [DFF][DM])
// z = 5:    W2 ([DFF][DM] -> [DM][DFF])  (swapped corner mapping)
// grid (64, 16, 6), block 256. float4 reads, uint2(4xhalf) writes.
__global__ void transpose_all_kernel(const float* __restrict__ Wq, const float* __restrict__ Wk,
                                     const float* __restrict__ Wv, const float* __restrict__ Wo,
                                     const float* __restrict__ W1, const float* __restrict__ W2,
                                     __half* __restrict__ oq, __half* __restrict__ ok,
                                     __half* __restrict__ ov, __half* __restrict__ oo,
                                     __half* __restrict__ o1, __half* __restrict__ o2)
{
    __shared__ float tile[64][65];
    int z = blockIdx.z;
    const float* in; __half* out; int K, N, n0, k0;
    if (z < 4) {
        if (blockIdx.x >= DM/64) return;
        in  = (z == 0) ? Wq : (z == 1) ? Wk : (z == 2) ? Wv : Wo;
        out = (z == 0) ? oq : (z == 1) ? ok : (z == 2) ? ov : oo;
        K = DM; N = DM; n0 = blockIdx.x * 64; k0 = blockIdx.y * 64;
    } else if (z == 4) {
        in = W1; out = o1; K = DM;  N = DFF; n0 = blockIdx.x * 64; k0 = blockIdx.y * 64;
    } else {
        in = W2; out = o2; K = DFF; N = DM;  n0 = blockIdx.y * 64; k0 = blockIdx.x * 64;
    }
    int t = threadIdx.x;

    // read phase: 64x64 floats as 1024 float4 (4 per thread)
#pragma unroll
    for (int u = 0; u < 4; u++) {
        int idx = t + u * 256;
        int row = idx >> 4, c4 = idx & 15;
        float4 v = *(const float4*)(in + (size_t)(k0 + row) * N + n0 + c4 * 4);
        tile[row][c4*4 + 0] = v.x;
        tile[row][c4*4 + 1] = v.y;
        tile[row][c4*4 + 2] = v.z;
        tile[row][c4*4 + 3] = v.w;
    }
    __syncthreads();

    // write phase: 64 output rows of 64 halves, as 1024 uint2 (4 per thread)
#pragma unroll
    for (int u = 0; u < 4; u++) {
        int idx = t + u * 256;
        int i = idx >> 4, c = idx & 15;
        float t0 = tile[c*4 + 0][i];
        float t1 = tile[c*4 + 1][i];
        float t2 = tile[c*4 + 2][i];
        float t3 = tile[c*4 + 3][i];
        uint2 w = make_uint2(pack_h2(t0, t1), pack_h2(t2, t3));
        *(uint2*)(out + (size_t)(n0 + i) * K + k0 + c * 4) = w;
    }
}

// ---------------- rope table build ----------------
__global__ void rope_table_kernel(float* __restrict__ cs, float* __restrict__ sn)
{
    int idx = blockIdx.x * blockDim.x + threadIdx.x;
    if (idx >= LL * 32) return;
    int i = idx & 31;
    int l = idx >> 5;
    double invf = pow(10000.0, -(double)i / 32.0);
    double ang = (double)l * invf;
    cs[idx] = (float)cos(ang);
    sn[idx] = (float)sin(ang);
}

// ---------------- LayerNorm (fp32 in, half out) ----------------
__global__ void ln_kernel(const float* __restrict__ x, const float* __restrict__ g,
                          const float* __restrict__ b, __half* __restrict__ y)
{
    int row = blockIdx.x;
    int t = threadIdx.x;
    const float4* xr = (const float4*)(x + (size_t)row * DM);
    float4 v = xr[t];
    float s  = v.x + v.y + v.z + v.w;
    float ss = v.x*v.x + v.y*v.y + v.z*v.z + v.w*v.w;
#pragma unroll
    for (int o = 16; o; o >>= 1) {
        s  += __shfl_xor_sync(0xffffffffu, s,  o);
        ss += __shfl_xor_sync(0xffffffffu, ss, o);
    }
    __shared__ float sh_s[8], sh_ss[8];
    int w = t >> 5, lane = t & 31;
    if (lane == 0) { sh_s[w] = s; sh_ss[w] = ss; }
    __syncthreads();
    if (t < 32) {
        s  = (t < 8) ? sh_s[t]  : 0.f;
        ss = (t < 8) ? sh_ss[t] : 0.f;
#pragma unroll
        for (int o = 4; o; o >>= 1) {
            s  += __shfl_xor_sync(0xffffffffu, s,  o);
            ss += __shfl_xor_sync(0xffffffffu, ss, o);
        }
        if (t == 0) { sh_s[0] = s; sh_ss[0] = ss; }
    }
    __syncthreads();
    float mu  = sh_s[0] * (1.f / DM);
    float var = sh_ss[0] * (1.f / DM) - mu * mu;
    float inv = rsqrtf(var + LN_EPS);
    float4 gv = ((const float4*)g)[t];
    float4 bv = ((const float4*)b)[t];
    uint32_t lo = pack_h2((v.x - mu) * inv * gv.x + bv.x,
                          (v.y - mu) * inv * gv.y + bv.y);
    uint32_t hi = pack_h2((v.z - mu) * inv * gv.z + bv.z,
                          (v.w - mu) * inv * gv.w + bv.w);
    ((uint2*)(y + (size_t)row * DM))[t] = make_uint2(lo, hi);
}

// ---------------- RoPE (heads < 8) + q scale, table-driven ----------------
__global__ void rope_h_kernel(__half* __restrict__ q, __half* __restrict__ k,
                              const float* __restrict__ cs_t, const float* __restrict__ sn_t)
{
    int idx = blockIdx.x * blockDim.x + threadIdx.x;
    const int total = NTOK * NH * (HD / 2);
    if (idx >= total) return;
    int i   = idx & 31;
    int h   = (idx >> 5) & 15;
    int tok = idx >> 9;
    int l   = tok & (LL - 1);
    size_t base = (size_t)tok * DM + h * HD + 2 * i;

    float q1 = __half2float(q[base]), q2 = __half2float(q[base + 1]);
    if (h < 8) {
        float cs = cs_t[l * 32 + i];
        float sn = sn_t[l * 32 + i];
        float k1 = __half2float(k[base]), k2 = __half2float(k[base + 1]);
        float qe = q1 * cs - q2 * sn;
        float qo = q1 * sn + q2 * cs;
        q1 = qe; q2 = qo;
        k[base]     = __float2half_rn(k1 * cs - k2 * sn);
        k[base + 1] = __float2half_rn(k1 * sn + k2 * cs);
    }
    q[base]     = __float2half_rn(q1 * 0.125f);
    q[base + 1] = __float2half_rn(q2 * 0.125f);
}

// ---------------- fp16 tensor-core GEMM (R13 exact) ----------------
#define AS_H 40
#define STAGE_H (128*AS_H*2)
#define HGEMM_SMEM (3*STAGE_H*2)

template<bool RELU, bool RES, bool HALF_OUT>
__global__ __launch_bounds__(128, 2)
void hgemm(const __half* __restrict__ A, const __half* __restrict__ Bt,
           const float* __restrict__ bias, const float* __restrict__ res,
           void* __restrict__ Cv, int M, int N, int K)
{
    extern __shared__ __half hsm[];
    int t = threadIdx.x;
    int wid = t >> 5, lane = t & 31;
    int g = lane >> 2, tq = lane & 3;
    int m0 = blockIdx.y * 128, n0 = blockIdx.x * 128;
    int wm = (wid >> 1) * 64;
    int wn = (wid & 1) * 64;

    float acc[4][8][4];
#pragma unroll
    for (int i = 0; i < 4; i++)
#pragma unroll
        for (int j = 0; j < 8; j++)
#pragma unroll
            for (int c = 0; c < 4; c++) acc[i][j][c] = 0.f;

    const int NK = K >> 5;

#pragma unroll
    for (int s = 0; s < 2; s++) {
        __half* as = hsm + s * STAGE_H;
        __half* bs = as + 128 * AS_H;
        int kb = s << 5;
#pragma unroll
        for (int u = 0; u < 4; u++) {
            int i = t + u * 128;
            int row = i >> 2, ch = i & 3;
            cp16(&as[row*AS_H + ch*8], A  + (size_t)(m0 + row) * K + kb + ch * 8);
            cp16(&bs[row*AS_H + ch*8], Bt + (size_t)(n0 + row) * K + kb + ch * 8);
        }
        CP_COMMIT();
    }

    for (int j = 0; j < NK; j++) {
        if (j + 2 < NK) { CP_WAIT1(); } else { CP_WAIT0(); }
        __syncthreads();

        int buf = j % 3;
        const uint32_t* as = (const uint32_t*)(hsm + buf * STAGE_H);
        const uint32_t* bs = as + 128 * (AS_H/2);

#pragma unroll
        for (int kf = 0; kf < 2; kf++) {
            uint32_t bf[8][2];
#pragma unroll
            for (int nf = 0; nf < 8; nf++) {
                bf[nf][0] = bs[(wn + nf*8 + g)*(AS_H/2) + kf*8 + tq];
                bf[nf][1] = bs[(wn + nf*8 + g)*(AS_H/2) + kf*8 + tq + 4];
            }
#pragma unroll
            for (int mf = 0; mf < 4; mf++) {
                int row = wm + mf * 16;
                uint32_t a0 = as[(row + g)    *(AS_H/2) + kf*8 + tq];
                uint32_t a1 = as[(row + g + 8)*(AS_H/2) + kf*8 + tq];
                uint32_t a2 = as[(row + g)    *(AS_H/2) + kf*8 + tq + 4];
                uint32_t a3 = as[(row + g + 8)*(AS_H/2) + kf*8 + tq + 4];
#pragma unroll
                for (int nf = 0; nf < 8; nf++)
                    mma16(acc[mf][nf][0], acc[mf][nf][1], acc[mf][nf][2], acc[mf][nf][3],
                          a0, a1, a2, a3, bf[nf][0], bf[nf][1]);
            }
        }

        if (j + 2 < NK) {
            int s = (j + 2) % 3;
            __half* asw = hsm + s * STAGE_H;
            __half* bsw = asw + 128 * AS_H;
            int kb = (j + 2) << 5;
#pragma unroll
            for (int u = 0; u < 4; u++) {
                int i = t + u * 128;
                int row = i >> 2, ch = i & 3;
                cp16(&asw[row*AS_H + ch*8], A  + (size_t)(m0 + row) * K + kb + ch * 8);
                cp16(&bsw[row*AS_H + ch*8], Bt + (size_t)(n0 + row) * K + kb + ch * 8);
            }
            CP_COMMIT();
        }
    }

#pragma unroll
    for (int mf = 0; mf < 4; mf++) {
#pragma unroll
        for (int nf = 0; nf < 8; nf++) {
            int r0 = m0 + wm + mf*16 + g;
            int r1 = r0 + 8;
            int cN = n0 + wn + nf*8 + 2*tq;
            float b0v = bias[cN], b1v = bias[cN + 1];
            float v0 = acc[mf][nf][0] + b0v;
            float v1 = acc[mf][nf][1] + b1v;
            float v2 = acc[mf][nf][2] + b0v;
            float v3 = acc[mf][nf][3] + b1v;
            if (RES) {
                v0 += res[(size_t)r0 * N + cN];     v1 += res[(size_t)r0 * N + cN + 1];
                v2 += res[(size_t)r1 * N + cN];     v3 += res[(size_t)r1 * N + cN + 1];
            }
            if (RELU) {
                v0 = fmaxf(v0, 0.f); v1 = fmaxf(v1, 0.f);
                v2 = fmaxf(v2, 0.f); v3 = fmaxf(v3, 0.f);
            }
            if (HALF_OUT) {
                __half* C = (__half*)Cv;
                *(uint32_t*)(C + (size_t)r0 * N + cN) = pack_h2(v0, v1);
                *(uint32_t*)(C + (size_t)r1 * N + cN) = pack_h2(v2, v3);
            } else {
                float* C = (float*)Cv;
                *(float2*)(C + (size_t)r0 * N + cN) = make_float2(v0, v1);
                *(float2*)(C + (size_t)r1 * N + cN) = make_float2(v2, v3);
            }
        }
    }
}

// ---------------- fp16 flash attention (R13 exact) ----------------
#define HS 72

__global__ __launch_bounds__(128, 3)
void attn_kernel(const __half* __restrict__ q, const __half* __restrict__ k,
                 const __half* __restrict__ v, __half* __restrict__ o)
{
    __shared__ __half Qs[64*HS];
    __shared__ __half Ks[2][64*HS];
    __shared__ __half Vs[2][64*HS];

    int qt = blockIdx.x, h = blockIdx.y, b = blockIdx.z;
    int t = threadIdx.x;
    int wid = t >> 5, lane = t & 31;
    int g = lane >> 2, tq = lane & 3;
    int wq = wid * 16;

    const __half* qbh = q + ((size_t)b * LL + qt * 64) * DM + h * HD;
    const __half* kbh = k + (size_t)b * LL * DM + h * HD;
    const __half* vbh = v + (size_t)b * LL * DM + h * HD;

#pragma unroll
    for (int u = 0; u < 4; u++) {
        int i = t + u * 128;
        int rr = i >> 3, c8 = i & 7;
        cp16(&Qs[rr*HS + c8*8],    qbh + (size_t)rr * DM + c8 * 8);
        cp16(&Ks[0][rr*HS + c8*8], kbh + (size_t)rr * DM + c8 * 8);
        cp16(&Vs[0][rr*HS + c8*8], vbh + (size_t)rr * DM + c8 * 8);
    }
    CP_COMMIT(); CP_WAIT0(); __syncthreads();

    uint32_t qa[4][4];
    {
        const uint32_t* qs = (const uint32_t*)Qs;
#pragma unroll
        for (int kf = 0; kf < 4; kf++) {
            qa[kf][0] = qs[(wq + g)    *(HS/2) + kf*8 + tq];
            qa[kf][1] = qs[(wq + g + 8)*(HS/2) + kf*8 + tq];
            qa[kf][2] = qs[(wq + g)    *(HS/2) + kf*8 + tq + 4];
            qa[kf][3] = qs[(wq + g + 8)*(HS/2) + kf*8 + tq + 4];
        }
    }

    int row_off = ((lane >> 3) & 1) * 8 + (lane & 7);
    int col_off = (lane >> 4) * 8;

    float oacc[8][4];
#pragma unroll
    for (int i = 0; i < 8; i++)
#pragma unroll
        for (int c = 0; c < 4; c++) oacc[i][c] = 0.f;
    float m0 = -1e30f, m1 = -1e30f, l0 = 0.f, l1 = 0.f;

    for (int j = 0; j < LL/64; j++) {
        int cur = j & 1;
        if (j + 1 < LL/64) {
            int nxt = cur ^ 1;
            const __half* kn = kbh + (size_t)(j + 1) * 64 * DM;
            const __half* vn = vbh + (size_t)(j + 1) * 64 * DM;
#pragma unroll
            for (int u = 0; u < 4; u++) {
                int i = t + u * 128;
                int rr = i >> 3, c8 = i & 7;
                cp16(&Ks[nxt][rr*HS + c8*8], kn + (size_t)rr * DM + c8 * 8);
                cp16(&Vs[nxt][rr*HS + c8*8], vn + (size_t)rr * DM + c8 * 8);
            }
        }
        CP_COMMIT();

        const uint32_t* ks = (const uint32_t*)Ks[cur];
        float sacc[8][4];
#pragma unroll
        for (int i = 0; i < 8; i++)
#pragma unroll
            for (int c = 0; c < 4; c++) sacc[i][c] = 0.f;

#pragma unroll
        for (int kf = 0; kf < 4; kf++) {
#pragma unroll
            for (int nf = 0; nf < 8; nf++) {
                uint32_t b0 = ks[(nf*8 + g)*(HS/2) + kf*8 + tq];
                uint32_t b1 = ks[(nf*8 + g)*(HS/2) + kf*8 + tq + 4];
                mma16(sacc[nf][0], sacc[nf][1], sacc[nf][2], sacc[nf][3],
                      qa[kf][0], qa[kf][1], qa[kf][2], qa[kf][3], b0, b1);
            }
        }

        float mx0 = -1e30f, mx1 = -1e30f;
#pragma unroll
        for (int nf = 0; nf < 8; nf++) {
            mx0 = fmaxf(mx0, fmaxf(sacc[nf][0], sacc[nf][1]));
            mx1 = fmaxf(mx1, fmaxf(sacc[nf][2], sacc[nf][3]));
        }
        mx0 = fmaxf(mx0, __shfl_xor_sync(0xffffffffu, mx0, 1));
        mx0 = fmaxf(mx0, __shfl_xor_sync(0xffffffffu, mx0, 2));
        mx1 = fmaxf(mx1, __shfl_xor_sync(0xffffffffu, mx1, 1));
        mx1 = fmaxf(mx1, __shfl_xor_sync(0xffffffffu, mx1, 2));
        float mn0 = fmaxf(m0, mx0), mn1 = fmaxf(m1, mx1);
        float al0 = __expf(m0 - mn0), al1 = __expf(m1 - mn1);

        uint32_t pa[8][2];
        float sum0 = 0.f, sum1 = 0.f;
#pragma unroll
        for (int nf = 0; nf < 8; nf++) {
            float p0 = __expf(sacc[nf][0] - mn0);
            float p1 = __expf(sacc[nf][1] - mn0);
            float p2 = __expf(sacc[nf][2] - mn1);
            float p3 = __expf(sacc[nf][3] - mn1);
            sum0 += p0 + p1;
            sum1 += p2 + p3;
            pa[nf][0] = pack_h2(p0, p1);
            pa[nf][1] = pack_h2(p2, p3);
        }
        sum0 += __shfl_xor_sync(0xffffffffu, sum0, 1);
        sum0 += __shfl_xor_sync(0xffffffffu, sum0, 2);
        sum1 += __shfl_xor_sync(0xffffffffu, sum1, 1);
        sum1 += __shfl_xor_sync(0xffffffffu, sum1, 2);
        l0 = l0 * al0 + sum0;
        l1 = l1 * al1 + sum1;
        m0 = mn0; m1 = mn1;
#pragma unroll
        for (int nf = 0; nf < 8; nf++) {
            oacc[nf][0] *= al0; oacc[nf][1] *= al0;
            oacc[nf][2] *= al1; oacc[nf][3] *= al1;
        }

        uint32_t vs_base = (uint32_t)__cvta_generic_to_shared(&Vs[cur][0]);
#pragma unroll
        for (int kf = 0; kf < 4; kf++) {
            uint32_t a0 = pa[2*kf][0],   a1 = pa[2*kf][1];
            uint32_t a2 = pa[2*kf+1][0], a3 = pa[2*kf+1][1];
#pragma unroll
            for (int np = 0; np < 4; np++) {
                uint32_t addr = vs_base +
                    (uint32_t)(((kf*16 + row_off)*HS + np*16 + col_off) * 2);
                uint32_t r0, r1, r2, r3;
                ldmx4t(r0, r1, r2, r3, addr);
                mma16(oacc[2*np][0],   oacc[2*np][1],   oacc[2*np][2],   oacc[2*np][3],
                      a0, a1, a2, a3, r0, r1);
                mma16(oacc[2*np+1][0], oacc[2*np+1][1], oacc[2*np+1][2], oacc[2*np+1][3],
                      a0, a1, a2, a3, r2, r3);
            }
        }

        CP_WAIT0();
        __syncthreads();
    }

    float inv0 = 1.f / l0, inv1 = 1.f / l1;
    size_t row0 = (size_t)b * LL + qt * 64 + wq + g;
    size_t row1 = row0 + 8;
#pragma unroll
    for (int nf = 0; nf < 8; nf++) {
        int cN = h * HD + nf*8 + 2*tq;
        *(uint32_t*)(o + row0 * DM + cN) = pack_h2(oacc[nf][0] * inv0, oacc[nf][1] * inv0);
        *(uint32_t*)(o + row1 * DM + cN) = pack_h2(oacc[nf][2] * inv1, oacc[nf][3] * inv1);
    }
}

// ---------------- launcher ----------------
extern "C" void kernel_launch(void* const* d_in, const int* in_sizes, int n_in,
                              void* d_out, int out_size)
{
    const float* x     = (const float*)d_in[0];
    const float* Wq    = (const float*)d_in[1];
    const float* bq    = (const float*)d_in[2];
    const float* Wk    = (const float*)d_in[3];
    const float* bk    = (const float*)d_in[4];
    const float* Wv    = (const float*)d_in[5];
    const float* bv    = (const float*)d_in[6];
    const float* Wo    = (const float*)d_in[7];
    const float* bo    = (const float*)d_in[8];
    const float* ln1_g = (const float*)d_in[9];
    const float* ln1_b = (const float*)d_in[10];
    const float* ln2_g = (const float*)d_in[11];
    const float* ln2_b = (const float*)d_in[12];
    const float* W1    = (const float*)d_in[13];
    const float* b1    = (const float*)d_in[14];
    const float* W2    = (const float*)d_in[15];
    const float* b2    = (const float*)d_in[16];
    float* out = (float*)d_out;

    float *x2, *cs_t, *sn_t;
    __half *xh, *xnh, *qh, *kh, *vh, *oh, *xn2h, *hbh;
    __half *wqh, *wkh, *wvh, *woh, *w1h, *w2h;
    cudaGetSymbolAddress((void**)&x2,   g_x2);
    cudaGetSymbolAddress((void**)&xh,   g_xh);
    cudaGetSymbolAddress((void**)&xnh,  g_xnh);
    cudaGetSymbolAddress((void**)&qh,   g_qh);
    cudaGetSymbolAddress((void**)&kh,   g_kh);
    cudaGetSymbolAddress((void**)&vh,   g_vh);
    cudaGetSymbolAddress((void**)&oh,   g_oh);
    cudaGetSymbolAddress((void**)&xn2h, g_xn2h);
    cudaGetSymbolAddress((void**)&hbh,  g_hbh);
    cudaGetSymbolAddress((void**)&wqh,  g_wqh);
    cudaGetSymbolAddress((void**)&wkh,  g_wkh);
    cudaGetSymbolAddress((void**)&wvh,  g_wvh);
    cudaGetSymbolAddress((void**)&woh,  g_woh);
    cudaGetSymbolAddress((void**)&w1h,  g_w1h);
    cudaGetSymbolAddress((void**)&w2h,  g_w2h);
    cudaGetSymbolAddress((void**)&cs_t, g_cs);
    cudaGetSymbolAddress((void**)&sn_t, g_sn);

    static bool attr_set = false;
    if (!attr_set) {
        cudaFuncSetAttribute((const void*)hgemm<false,false,true>, cudaFuncAttributeMaxDynamicSharedMemorySize, HGEMM_SMEM);
        cudaFuncSetAttribute((const void*)hgemm<false,true,false>, cudaFuncAttributeMaxDynamicSharedMemorySize, HGEMM_SMEM);
        cudaFuncSetAttribute((const void*)hgemm<true,false,true>,  cudaFuncAttributeMaxDynamicSharedMemorySize, HGEMM_SMEM);
        attr_set = true;
    }

    // conditioning: x -> half; rope tables; all 6 weight transposes in one launch
    f2h_kernel<<<(NTOK*DM/4 + 255)/256, 256>>>(x, xh, NTOK*DM/4);
    rope_table_kernel<<<(LL*32 + 255)/256, 256>>>(cs_t, sn_t);
    transpose_all_kernel<<<dim3(DFF/64, DM/64, 6), 256>>>(Wq, Wk, Wv, Wo, W1, W2,
                                                          wqh, wkh, wvh, woh, w1h, w2h);

    ln_kernel<<<NTOK, 256>>>(x, ln1_g, ln1_b, xnh);

    dim3 g1(DM / 128, NTOK / 128);     // (8, 32)
    hgemm<false,false,true><<<g1, 128, HGEMM_SMEM>>>(xnh, wqh, bq, nullptr, qh, NTOK, DM, DM);
    hgemm<false,false,true><<<g1, 128, HGEMM_SMEM>>>(xh,  wkh, bk, nullptr, kh, NTOK, DM, DM);
    hgemm<false,false,true><<<g1, 128, HGEMM_SMEM>>>(xh,  wvh, bv, nullptr, vh, NTOK, DM, DM);

    const int pairs = NTOK * NH * (HD / 2);
    rope_h_kernel<<<(pairs + 255) / 256, 256>>>(qh, kh, cs_t, sn_t);

    dim3 ga(LL / 64, NH, BB);
    attn_kernel<<<ga, 128>>>(qh, kh, vh, oh);

    hgemm<false,true,false><<<g1, 128, HGEMM_SMEM>>>(oh, woh, bo, x, x2, NTOK, DM, DM);

    ln_kernel<<<NTOK, 256>>>(x2, ln2_g, ln2_b, xn2h);

    dim3 g2(DFF / 128, NTOK / 128);    // (32, 32)
    hgemm<true,false,true><<<g2, 128, HGEMM_SMEM>>>(xn2h, w1h, b1, nullptr, hbh, NTOK, DFF, DM);
    hgemm<false,true,false><<<g1, 128, HGEMM_SMEM>>>(hbh, w2h, b2, x2, out, NTOK, DM, DFF);
}